// round 3
// baseline (speedup 1.0000x reference)
#include <cuda_runtime.h>

#define BB   8
#define NPT  4096
#define DD   64
#define KP   1024
#define NNB  16
#define CC   128
#define CIN  67            // D + 3
#define MT   (BB*KP*NNB)   // 131072 rows
#define EPSBN 1e-5f

// ---------------- scratch ----------------
__device__ float g_h1[(size_t)MT*CC];
__device__ float g_h2[(size_t)MT*CC];
__device__ int   g_knn[MT];
__device__ float g_nxyz[BB*KP*3];
__device__ float g_W1T[CIN*CC];
__device__ float g_W2T[CC*CC];
__device__ float g_part[2*1024*CC];
__device__ float g_scale[2][CC];
__device__ float g_shift[2][CC];

// ---------------- helpers ----------------
__device__ __forceinline__ unsigned redux_max_u32(unsigned v) {
    unsigned r; asm("redux.sync.max.u32 %0,%1,0xffffffff;" : "=r"(r) : "r"(v)); return r;
}
__device__ __forceinline__ unsigned redux_min_u32(unsigned v) {
    unsigned r; asm("redux.sync.min.u32 %0,%1,0xffffffff;" : "=r"(r) : "r"(v)); return r;
}
__device__ __forceinline__ void fma2(unsigned long long& d, unsigned long long a, unsigned long long b) {
    asm("fma.rn.f32x2 %0,%1,%2,%0;" : "+l"(d) : "l"(a), "l"(b));
}
__device__ __forceinline__ float2 u2f(unsigned long long v) {
    float2 f; asm("mov.b64 {%0,%1},%2;" : "=f"(f.x), "=f"(f.y) : "l"(v)); return f;
}

// ---------------- FPS: one block/batch, 1024 threads, ONE barrier/iter ----------------
__global__ void fps_kernel(const float* __restrict__ xyz, float* __restrict__ outx) {
    extern __shared__ float fsm[];
    float* sx = fsm;
    float* sy = fsm + NPT;
    float* sz = fsm + 2*NPT;
    unsigned* swv = (unsigned*)(fsm + 3*NPT);   // [2][32] double-buffered
    unsigned* swi = swv + 64;                    // [2][32]

    const int b   = blockIdx.x;
    const int tid = threadIdx.x;                 // 1024
    const int lane = tid & 31, warp = tid >> 5;
    const float* base = xyz + (size_t)b*NPT*3;

    float px[4], py[4], pz[4], dist[4];
#pragma unroll
    for (int i = 0; i < 4; i++) {
        int p = tid + i*1024;
        float x = base[p*3+0], y = base[p*3+1], z = base[p*3+2];
        px[i] = x; py[i] = y; pz[i] = z;
        sx[p] = x; sy[p] = y; sz[p] = z;
        dist[i] = 1e10f;
    }
    __syncthreads();

    int far = 0;
    for (int t = 0; t < KP; t++) {
        float cx = sx[far], cy = sy[far], cz = sz[far];
        if (tid == 0) {
            int o = (b*KP + t)*3;
            g_nxyz[o+0] = cx; g_nxyz[o+1] = cy; g_nxyz[o+2] = cz;
            if (outx) { outx[o+0] = cx; outx[o+1] = cy; outx[o+2] = cz; }
        }
        float bv; unsigned bi;
#pragma unroll
        for (int i = 0; i < 4; i++) {
            float dx = px[i]-cx, dy = py[i]-cy, dz = pz[i]-cz;
            float d  = dx*dx + dy*dy + dz*dz;
            dist[i]  = fminf(dist[i], d);
            if (i == 0) { bv = dist[0]; bi = (unsigned)tid; }
            else if (dist[i] > bv) { bv = dist[i]; bi = (unsigned)(tid + i*1024); }
        }
        unsigned vb = __float_as_uint(bv);
        unsigned wm = redux_max_u32(vb);
        unsigned ci = (vb == wm) ? bi : 0xFFFFFFFFu;
        unsigned wi = redux_min_u32(ci);
        const int par = (t & 1) * 32;
        if (lane == 0) { swv[par + warp] = wm; swi[par + warp] = wi; }
        __syncthreads();
        // every warp computes the block argmax redundantly -> far in registers
        unsigned v  = swv[par + lane];
        unsigned ii = swi[par + lane];
        unsigned m  = redux_max_u32(v);
        unsigned c2 = (v == m) ? ii : 0xFFFFFFFFu;
        far = (int)redux_min_u32(c2);
    }
}

// ---------------- kNN: one warp per center ----------------
__global__ void knn_kernel(const float* __restrict__ xyz) {
    extern __shared__ float sm[];
    float* spx = sm;
    float* spy = sm + NPT;
    float* spz = sm + 2*NPT;
    float* sn  = sm + 3*NPT;

    int cid0 = blockIdx.x * 4;
    int b    = cid0 >> 10;
    const float* base = xyz + (size_t)b*NPT*3;
    for (int j = threadIdx.x; j < NPT; j += 128) {
        float x = base[j*3+0], y = base[j*3+1], z = base[j*3+2];
        spx[j] = x; spy[j] = y; spz[j] = z;
        sn[j]  = x*x + y*y + z*z;
    }
    __syncthreads();

    int w = threadIdx.x >> 5, l = threadIdx.x & 31;
    int cid = cid0 + w;
    float cx = g_nxyz[cid*3+0], cy = g_nxyz[cid*3+1], cz = g_nxyz[cid*3+2];
    float cn = cx*cx + cy*cy + cz*cz;

    float bd[16]; int bi[16];
#pragma unroll
    for (int k = 0; k < 16; k++) { bd[k] = 3.4e38f; bi[k] = 1 << 30; }

    for (int j = l; j < NPT; j += 32) {
        float dot = cx*spx[j] + cy*spy[j] + cz*spz[j];
        float sq  = cn + sn[j] - 2.0f*dot;
        if (sq < bd[15] || (sq == bd[15] && j < bi[15])) {
            float d = sq; int ii = j;
#pragma unroll
            for (int k = 0; k < 16; k++) {
                bool sw = (d < bd[k]) || (d == bd[k] && ii < bi[k]);
                float td = bd[k]; int ti = bi[k];
                if (sw) { bd[k] = d; bi[k] = ii; d = td; ii = ti; }
            }
        }
    }
    for (int s = 0; s < 16; s++) {
        float v = bd[0]; int vi = bi[0];
#pragma unroll
        for (int o = 16; o > 0; o >>= 1) {
            float ov = __shfl_xor_sync(0xffffffffu, v, o);
            int   oi = __shfl_xor_sync(0xffffffffu, vi, o);
            if (ov < v || (ov == v && oi < vi)) { v = ov; vi = oi; }
        }
        if (bd[0] == v && bi[0] == vi) {
#pragma unroll
            for (int k = 0; k < 15; k++) { bd[k] = bd[k+1]; bi[k] = bi[k+1]; }
            bd[15] = 3.4e38f; bi[15] = 1 << 30;
        }
        if (l == 0) g_knn[cid*16 + s] = vi;
    }
}

// ---------------- pre-transpose weights (k-major) ----------------
__global__ void wt_kernel(const float* __restrict__ W1, const float* __restrict__ W2) {
    for (int idx = threadIdx.x; idx < CC*CIN; idx += blockDim.x) {
        int o = idx / CIN, c = idx - o*CIN;
        g_W1T[c*CC + o] = W1[idx];
    }
    for (int idx = threadIdx.x; idx < CC*CC; idx += blockDim.x) {
        int o = idx >> 7, c = idx & 127;
        g_W2T[c*CC + o] = W2[idx];
    }
}

#define SA2_STRIDE 264

// stats epilogue shared by both GEMMs: per-block column sum/sumsq -> g_part
__device__ __forceinline__ void stats_epilogue(float* red, const float s8[8], const float q8[8],
                                               int ty, int tx, int tid, int blk) {
    // red: >= 16*256 floats (reuses sA2 region)
#pragma unroll
    for (int j = 0; j < 8; j++) {
        red[ty*256 + tx*8 + j]       = s8[j];
        red[ty*256 + 128 + tx*8 + j] = q8[j];
    }
    __syncthreads();
    if (tid < 128) {
        float s = 0.0f, q = 0.0f;
#pragma unroll
        for (int y = 0; y < 16; y++) {
            s += red[y*256 + tid];
            q += red[y*256 + 128 + tid];
        }
        g_part[blk*CC + tid]           = s;
        g_part[1024*CC + blk*CC + tid] = q;
    }
}

// ---------------- GEMM1 (fused gather + stats): h1 = gather(h0) @ W1^T + b1 ----------------
__global__ void gemm1_kernel(const float* __restrict__ xyz,
                             const float* __restrict__ points,
                             const float* __restrict__ bias) {
    extern __shared__ float sm[];
    float* sA2 = sm;                          // CIN * 264
    float* sB  = sm + CIN*SA2_STRIDE;         // CIN * 128
    __shared__ int   s_nid[128];
    __shared__ float s_ctr[128*3];

    const int m0 = blockIdx.x * 128;
    const int tid = threadIdx.x;              // 256

    if (tid < 128) {
        int gw = m0 + tid;
        s_nid[tid] = g_knn[gw];
        int bk = gw >> 4;
        s_ctr[tid*3+0] = g_nxyz[bk*3+0];
        s_ctr[tid*3+1] = g_nxyz[bk*3+1];
        s_ctr[tid*3+2] = g_nxyz[bk*3+2];
    }
    __syncthreads();

    for (int idx = tid; idx < 128*CIN; idx += 256) {
        int r = idx / CIN, c = idx - r*CIN;
        int nid = s_nid[r];
        int b = (m0 + r) >> 14;
        float v;
        if (c < 3) v = xyz[((size_t)b*NPT + nid)*3 + c] - s_ctr[r*3 + c];
        else       v = points[((size_t)b*NPT + nid)*DD + (c-3)];
        *(float2*)(sA2 + c*SA2_STRIDE + 2*r) = make_float2(v, v);
    }
    for (int idx = tid; idx < CIN*CC; idx += 256) sB[idx] = g_W1T[idx];
    __syncthreads();

    const int ty = tid >> 4, tx = tid & 15;
    unsigned long long acc[8][4];
#pragma unroll
    for (int i = 0; i < 8; i++)
#pragma unroll
        for (int j = 0; j < 4; j++) acc[i][j] = 0ull;

#pragma unroll 2
    for (int k = 0; k < CIN; k++) {
        const float* pa = sA2 + k*SA2_STRIDE + ty*16;
        ulonglong2 a01 = *(const ulonglong2*)(pa + 0);
        ulonglong2 a23 = *(const ulonglong2*)(pa + 4);
        ulonglong2 a45 = *(const ulonglong2*)(pa + 8);
        ulonglong2 a67 = *(const ulonglong2*)(pa + 12);
        ulonglong2 b01 = *(const ulonglong2*)(sB + k*CC + tx*8);
        ulonglong2 b23 = *(const ulonglong2*)(sB + k*CC + tx*8 + 4);
        unsigned long long av[8] = {a01.x,a01.y,a23.x,a23.y,a45.x,a45.y,a67.x,a67.y};
        unsigned long long bv[4] = {b01.x,b01.y,b23.x,b23.y};
#pragma unroll
        for (int i = 0; i < 8; i++)
#pragma unroll
            for (int j = 0; j < 4; j++) fma2(acc[i][j], av[i], bv[j]);
    }
    float4 q0 = *(const float4*)(bias + tx*8);
    float4 q1 = *(const float4*)(bias + tx*8 + 4);
    float bb[8] = {q0.x,q0.y,q0.z,q0.w,q1.x,q1.y,q1.z,q1.w};
    float s8[8] = {0,0,0,0,0,0,0,0}, sq8[8] = {0,0,0,0,0,0,0,0};
#pragma unroll
    for (int i = 0; i < 8; i++) {
        size_t ro = (size_t)(m0 + ty*8 + i)*CC + tx*8;
        float2 p0 = u2f(acc[i][0]), p1 = u2f(acc[i][1]);
        float2 p2 = u2f(acc[i][2]), p3 = u2f(acc[i][3]);
        float v[8] = {p0.x+bb[0], p0.y+bb[1], p1.x+bb[2], p1.y+bb[3],
                      p2.x+bb[4], p2.y+bb[5], p3.x+bb[6], p3.y+bb[7]};
#pragma unroll
        for (int j = 0; j < 8; j++) { s8[j] += v[j]; sq8[j] = fmaf(v[j], v[j], sq8[j]); }
        *(float4*)(g_h1 + ro)     = make_float4(v[0],v[1],v[2],v[3]);
        *(float4*)(g_h1 + ro + 4) = make_float4(v[4],v[5],v[6],v[7]);
    }
    __syncthreads();
    stats_epilogue(sA2, s8, sq8, ty, tx, tid, blockIdx.x);
}

// ---------------- GEMM2 (fused stats): h2 = relu(bn(h1)) @ W2^T + b2 ----------------
__global__ void gemm2_kernel(const float* __restrict__ bias) {
    extern __shared__ float sm[];
    float* sA2 = sm;                          // 64 * 264
    float* sB  = sm + 64*SA2_STRIDE;          // 64 * 128
    const int m0 = blockIdx.x * 128;
    const int tid = threadIdx.x;
    const int ty = tid >> 4, tx = tid & 15;

    unsigned long long acc[8][4];
#pragma unroll
    for (int i = 0; i < 8; i++)
#pragma unroll
        for (int j = 0; j < 4; j++) acc[i][j] = 0ull;

    for (int kc = 0; kc < CC; kc += 64) {
        __syncthreads();
        for (int idx = tid; idx < 128*64; idx += 256) {
            int r = idx >> 6, c = idx & 63;
            int ch = kc + c;
            float x = g_h1[(size_t)(m0 + r)*CC + ch];
            float v = fmaxf(fmaf(x, g_scale[0][ch], g_shift[0][ch]), 0.0f);
            *(float2*)(sA2 + c*SA2_STRIDE + 2*r) = make_float2(v, v);
        }
        for (int idx = tid; idx < 64*CC; idx += 256) sB[idx] = g_W2T[kc*CC + idx];
        __syncthreads();

#pragma unroll 2
        for (int k = 0; k < 64; k++) {
            const float* pa = sA2 + k*SA2_STRIDE + ty*16;
            ulonglong2 a01 = *(const ulonglong2*)(pa + 0);
            ulonglong2 a23 = *(const ulonglong2*)(pa + 4);
            ulonglong2 a45 = *(const ulonglong2*)(pa + 8);
            ulonglong2 a67 = *(const ulonglong2*)(pa + 12);
            ulonglong2 b01 = *(const ulonglong2*)(sB + k*CC + tx*8);
            ulonglong2 b23 = *(const ulonglong2*)(sB + k*CC + tx*8 + 4);
            unsigned long long av[8] = {a01.x,a01.y,a23.x,a23.y,a45.x,a45.y,a67.x,a67.y};
            unsigned long long bv[4] = {b01.x,b01.y,b23.x,b23.y};
#pragma unroll
            for (int i = 0; i < 8; i++)
#pragma unroll
                for (int j = 0; j < 4; j++) fma2(acc[i][j], av[i], bv[j]);
        }
    }
    float4 q0 = *(const float4*)(bias + tx*8);
    float4 q1 = *(const float4*)(bias + tx*8 + 4);
    float bb[8] = {q0.x,q0.y,q0.z,q0.w,q1.x,q1.y,q1.z,q1.w};
    float s8[8] = {0,0,0,0,0,0,0,0}, sq8[8] = {0,0,0,0,0,0,0,0};
#pragma unroll
    for (int i = 0; i < 8; i++) {
        size_t ro = (size_t)(m0 + ty*8 + i)*CC + tx*8;
        float2 p0 = u2f(acc[i][0]), p1 = u2f(acc[i][1]);
        float2 p2 = u2f(acc[i][2]), p3 = u2f(acc[i][3]);
        float v[8] = {p0.x+bb[0], p0.y+bb[1], p1.x+bb[2], p1.y+bb[3],
                      p2.x+bb[4], p2.y+bb[5], p3.x+bb[6], p3.y+bb[7]};
#pragma unroll
        for (int j = 0; j < 8; j++) { s8[j] += v[j]; sq8[j] = fmaf(v[j], v[j], sq8[j]); }
        *(float4*)(g_h2 + ro)     = make_float4(v[0],v[1],v[2],v[3]);
        *(float4*)(g_h2 + ro + 4) = make_float4(v[4],v[5],v[6],v[7]);
    }
    __syncthreads();
    stats_epilogue(sA2, s8, sq8, ty, tx, tid, blockIdx.x);
}

// ---------------- BN finalize ----------------
__global__ void bnfin_kernel(int layer, const float* __restrict__ g,
                             const float* __restrict__ be) {
    int ch = threadIdx.x;
    float s = 0.0f, sq = 0.0f;
#pragma unroll 8
    for (int i = 0; i < 1024; i++) {
        s  += g_part[i*CC + ch];
        sq += g_part[1024*CC + i*CC + ch];
    }
    float inv = 1.0f / (float)MT;
    float mean = s * inv;
    float var  = sq * inv - mean*mean;
    float rs   = rsqrtf(var + EPSBN);
    float sc   = rs * g[ch];
    g_scale[layer][ch] = sc;
    g_shift[layer][ch] = be[ch] - mean*sc;
}

// ---------------- final: relu(bn(h2)) max over NN ----------------
__global__ void final_kernel(float* __restrict__ out, int off) {
    int bk = blockIdx.x;
    int ch = threadIdx.x;
    const float* p = g_h2 + (size_t)bk*NNB*CC + ch;
    float sc = g_scale[1][ch], sh = g_shift[1][ch];
    float m = -3.4e38f;
#pragma unroll
    for (int s = 0; s < NNB; s++)
        m = fmaxf(m, fmaxf(fmaf(p[(size_t)s*CC], sc, sh), 0.0f));
    out[(size_t)off + (size_t)bk*CC + ch] = m;
}

// ---------------- launch ----------------
extern "C" void kernel_launch(void* const* d_in, const int* in_sizes, int n_in,
                              void* d_out, int out_size) {
    const float* xyz    = (const float*)d_in[0];
    const float* points = (const float*)d_in[1];
    const float* W1     = (const float*)d_in[2];
    const float* b1     = (const float*)d_in[3];
    const float* g1     = (const float*)d_in[4];
    const float* be1    = (const float*)d_in[5];
    const float* W2     = (const float*)d_in[6];
    const float* b2     = (const float*)d_in[7];
    const float* g2     = (const float*)d_in[8];
    const float* be2    = (const float*)d_in[9];
    float* out = (float*)d_out;

    const int has_xyz = (out_size >= BB*KP*3 + BB*KP*CC) ? 1 : 0;
    float* outx = has_xyz ? out : nullptr;
    const int poff = has_xyz ? BB*KP*3 : 0;

    const int fps_smem  = (3*NPT + 128)*(int)sizeof(float) + 16;
    const int knn_smem  = 4*NPT*(int)sizeof(float);
    const int g1_smem   = (CIN*SA2_STRIDE + CIN*CC)*(int)sizeof(float);
    const int g2_smem   = (64*SA2_STRIDE + 64*CC)*(int)sizeof(float);
    cudaFuncSetAttribute(fps_kernel,  cudaFuncAttributeMaxDynamicSharedMemorySize, fps_smem);
    cudaFuncSetAttribute(knn_kernel,  cudaFuncAttributeMaxDynamicSharedMemorySize, knn_smem);
    cudaFuncSetAttribute(gemm1_kernel,cudaFuncAttributeMaxDynamicSharedMemorySize, g1_smem);
    cudaFuncSetAttribute(gemm2_kernel,cudaFuncAttributeMaxDynamicSharedMemorySize, g2_smem);

    fps_kernel<<<BB, 1024, fps_smem>>>(xyz, outx);
    wt_kernel<<<1, 256>>>(W1, W2);
    knn_kernel<<<(BB*KP)/4, 128, knn_smem>>>(xyz);
    gemm1_kernel<<<MT/128, 256, g1_smem>>>(xyz, points, b1);
    bnfin_kernel<<<1, 128>>>(0, g1, be1);
    gemm2_kernel<<<MT/128, 256, g2_smem>>>(b2);
    bnfin_kernel<<<1, 128>>>(1, g2, be2);
    final_kernel<<<BB*KP, 128>>>(out, poff);
}